// round 2
// baseline (speedup 1.0000x reference)
#include <cuda_runtime.h>
#include <math.h>

#define NB 8
#define THREADS 128
#define FEAT 128
#define SEQ 32
#define NHEAD 4
#define HDIM 32
#define PAD_KV 132            // floats per staged row = 33 float4 (odd -> conflict-free LDS.128)
#define LN_EPS 1e-5f
#define INV_SQRT_D 0.17677669529663687f

// dynamic smem layout (float offsets)
#define OFF_Q    0            // NB*128  query rows; reused as out rows
#define OFF_QP   1024         // NB*128  projected q; reused as wv
#define OFF_T    2048         // NB*4*128 t vectors
#define OFF_ATTN 6144         // NB*128  attn [j][s*4+h]
#define OFF_U    7168         // NB*4*128 aggregated values
#define OFF_KV   11264        // 32*132 = 4224 floats; also Wk block staging (128*33)
#define OFF_SB   15488        // NB*4 score bias
#define SMEM_FLOATS 15520

__device__ __forceinline__ float warp_max(float v) {
#pragma unroll
    for (int o = 16; o; o >>= 1) v = fmaxf(v, __shfl_xor_sync(0xffffffffu, v, o));
    return v;
}
__device__ __forceinline__ float warp_sum(float v) {
#pragma unroll
    for (int o = 16; o; o >>= 1) v += __shfl_xor_sync(0xffffffffu, v, o);
    return v;
}

__global__ __launch_bounds__(THREADS)
void mha_fused_kernel(
    const float* __restrict__ query, const float* __restrict__ key,
    const float* __restrict__ value, const int* __restrict__ mask_idx,
    const float* __restrict__ Wq, const float* __restrict__ bq,
    const float* __restrict__ Wk, const float* __restrict__ bk,
    const float* __restrict__ Wv, const float* __restrict__ bv,
    const float* __restrict__ Wo, const float* __restrict__ bo,
    const float* __restrict__ gamma, const float* __restrict__ beta,
    float* __restrict__ out, int N)
{
    extern __shared__ float sm[];
    const int tid  = threadIdx.x;
    const int w    = tid >> 5;     // warp id == head id in score/softmax phase
    const int lane = tid & 31;
    const int n0   = blockIdx.x * NB;

    float* s_q    = sm + OFF_Q;
    float* s_qp   = sm + OFF_QP;
    float* s_t    = sm + OFF_T;
    float* s_attn = sm + OFF_ATTN;
    float* s_u    = sm + OFF_U;
    float* s_kv   = sm + OFF_KV;
    float* s_sb   = sm + OFF_SB;

    // ---- stage query rows ----
#pragma unroll
    for (int j = 0; j < NB; j++) {
        int n = n0 + j;
        s_q[j * FEAT + tid] = (n < N) ? query[(size_t)n * FEAT + tid] : 0.f;
    }
    __syncthreads();

    // ---- Phase A: qp = q @ Wq + bq  (thread = out feature, 8-node accumulators) ----
    {
        float acc[NB];
        float b = bq[tid];
#pragma unroll
        for (int j = 0; j < NB; j++) acc[j] = b;
#pragma unroll 4
        for (int f = 0; f < FEAT; f++) {
            float wgt = Wq[f * FEAT + tid];
#pragma unroll
            for (int j = 0; j < NB; j++) acc[j] = fmaf(s_q[j * FEAT + f], wgt, acc[j]);
        }
#pragma unroll
        for (int j = 0; j < NB; j++) s_qp[j * FEAT + tid] = acc[j];
    }
    __syncthreads();

    // ---- Phase B: t[j][h][f] = sum_d Wk[f, h*32+d] * qp[j, h*32+d] ----
    for (int h = 0; h < NHEAD; h++) {
        // stage Wk[:, h*32:(h+1)*32] as [128][32] stride-33 (transposed access later)
        for (int r = tid; r < FEAT * HDIM; r += THREADS) {
            int f = r >> 5, dd = r & 31;
            s_kv[f * 33 + dd] = Wk[f * FEAT + h * HDIM + dd];
        }
        __syncthreads();
        float acc[NB];
#pragma unroll
        for (int j = 0; j < NB; j++) acc[j] = 0.f;
#pragma unroll
        for (int dd = 0; dd < HDIM; dd++) {
            float wgt = s_kv[tid * 33 + dd];
#pragma unroll
            for (int j = 0; j < NB; j++)
                acc[j] = fmaf(s_qp[j * FEAT + h * HDIM + dd], wgt, acc[j]);
        }
#pragma unroll
        for (int j = 0; j < NB; j++) s_t[j * (NHEAD * FEAT) + h * FEAT + tid] = acc[j];
        __syncthreads();
    }

    // ---- score bias: sbias[j][h] = qp_h . bk_h ----
    if (tid < NB * NHEAD) {
        int j = tid >> 2, h = tid & 3;
        float s = 0.f;
        for (int dd = 0; dd < HDIM; dd++)
            s += s_qp[j * FEAT + h * HDIM + dd] * bk[h * HDIM + dd];
        s_sb[tid] = s;
    }
    __syncthreads();

    const float4* key4 = reinterpret_cast<const float4*>(key);
    const float4* val4 = reinterpret_cast<const float4*>(value);
    float4* s_kv4 = reinterpret_cast<float4*>(s_kv);

    // ---- Per-node: scores + softmax + value aggregation (ragged) ----
    for (int j = 0; j < NB; j++) {
        int n = n0 + j;
        if (n >= N) break;
        int midx = mask_idx[n];
        // midx == 0: in the reference, scores + (-1e9) rounds to exactly -1e9
        // for ALL positions (|score| << fp32 ulp at 1e9), so softmax is UNIFORM 1/SEQ.
        bool uniform = (midx == 0);
        int Sa = uniform ? SEQ : midx;

        if (!uniform) {
            // stage active key rows (coalesced float4 per warp-row)
            for (int r = tid; r < Sa * (FEAT / 4); r += THREADS) {
                int s = r >> 5, k = r & 31;
                s_kv4[s * 33 + k] = key4[((size_t)s * N + n) * (FEAT / 4) + k];
            }
            __syncthreads();

            // scores: warp = head, lane = seq position; then warp softmax
            float sc = -1e30f;
            float p  = 0.f;
            if (lane < Sa) {
                const float4* t4 = reinterpret_cast<const float4*>(s_t + j * (NHEAD * FEAT) + w * FEAT);
                float ax = 0.f, ay = 0.f, az = 0.f, aw = 0.f;
#pragma unroll 8
                for (int k = 0; k < FEAT / 4; k++) {
                    float4 kv = s_kv4[lane * 33 + k];
                    float4 tv = t4[k];
                    ax = fmaf(kv.x, tv.x, ax);
                    ay = fmaf(kv.y, tv.y, ay);
                    az = fmaf(kv.z, tv.z, az);
                    aw = fmaf(kv.w, tv.w, aw);
                }
                sc = (((ax + ay) + (az + aw)) + s_sb[j * 4 + w]) * INV_SQRT_D;
            }
            float m = warp_max(sc);
            if (lane < Sa) p = expf(sc - m);
            float denom = warp_sum(p);
            if (lane < Sa) s_attn[j * FEAT + lane * 4 + w] = p / denom;
        } else {
            // uniform attention over all SEQ positions
            s_attn[j * FEAT + lane * 4 + w] = 1.0f / SEQ;
        }
        __syncthreads();

        // stage active value rows
        for (int r = tid; r < Sa * (FEAT / 4); r += THREADS) {
            int s = r >> 5, k = r & 31;
            s_kv4[s * 33 + k] = val4[((size_t)s * N + n) * (FEAT / 4) + k];
        }
        __syncthreads();

        // u[j][h][f] = sum_{s<Sa} attn[s,h] * value[s,f]   (thread = f)
        {
            float a0 = 0.f, a1 = 0.f, a2 = 0.f, a3 = 0.f;
            for (int s = 0; s < Sa; s++) {
                float vv = s_kv[s * PAD_KV + tid];
                const float* ap = s_attn + j * FEAT + s * 4;
                a0 = fmaf(ap[0], vv, a0);
                a1 = fmaf(ap[1], vv, a1);
                a2 = fmaf(ap[2], vv, a2);
                a3 = fmaf(ap[3], vv, a3);
            }
            s_u[j * (NHEAD * FEAT) + 0 * FEAT + tid] = a0;
            s_u[j * (NHEAD * FEAT) + 1 * FEAT + tid] = a1;
            s_u[j * (NHEAD * FEAT) + 2 * FEAT + tid] = a2;
            s_u[j * (NHEAD * FEAT) + 3 * FEAT + tid] = a3;
        }
        __syncthreads();
    }

    // ---- Phase E: wv[j][o] = bv[o] + sum_f u[j][o/32][f] * Wv[f,o]  (into s_qp region) ----
    {
        float acc[NB];
        float b = bv[tid];
#pragma unroll
        for (int j = 0; j < NB; j++) acc[j] = b;
        const int h = tid >> 5;
#pragma unroll 4
        for (int f = 0; f < FEAT; f++) {
            float wgt = Wv[f * FEAT + tid];
#pragma unroll
            for (int j = 0; j < NB; j++)
                acc[j] = fmaf(s_u[j * (NHEAD * FEAT) + h * FEAT + f], wgt, acc[j]);
        }
#pragma unroll
        for (int j = 0; j < NB; j++) s_qp[j * FEAT + tid] = acc[j];   // s_wv
    }
    __syncthreads();

    // ---- Phase F: out[j][f'] = bo[f'] + sum_o wv[j][o] * Wo[o,f']  (into s_q region) ----
    {
        float acc[NB];
        float b = bo[tid];
#pragma unroll
        for (int j = 0; j < NB; j++) acc[j] = b;
#pragma unroll 4
        for (int o = 0; o < FEAT; o++) {
            float wgt = Wo[o * FEAT + tid];
#pragma unroll
            for (int j = 0; j < NB; j++)
                acc[j] = fmaf(s_qp[j * FEAT + o], wgt, acc[j]);
        }
#pragma unroll
        for (int j = 0; j < NB; j++) s_q[j * FEAT + tid] = acc[j];    // s_out
    }
    __syncthreads();

    // ---- Phase G: LayerNorm + residual (warp handles nodes w, w+4) ----
    for (int j = w; j < NB; j += 4) {
        int n = n0 + j;
        if (n >= N) continue;
        float v0 = s_q[j * FEAT + lane];
        float v1 = s_q[j * FEAT + lane + 32];
        float v2 = s_q[j * FEAT + lane + 64];
        float v3 = s_q[j * FEAT + lane + 96];
        float mu = warp_sum(v0 + v1 + v2 + v3) * (1.f / FEAT);
        float d0 = v0 - mu, d1 = v1 - mu, d2 = v2 - mu, d3 = v3 - mu;
        float var = warp_sum(d0 * d0 + d1 * d1 + d2 * d2 + d3 * d3) * (1.f / FEAT);
        float rstd = rsqrtf(var + LN_EPS);
        size_t base = (size_t)n * FEAT;
        out[base + lane]      = query[base + lane]      + d0 * rstd * gamma[lane]      + beta[lane];
        out[base + lane + 32] = query[base + lane + 32] + d1 * rstd * gamma[lane + 32] + beta[lane + 32];
        out[base + lane + 64] = query[base + lane + 64] + d2 * rstd * gamma[lane + 64] + beta[lane + 64];
        out[base + lane + 96] = query[base + lane + 96] + d3 * rstd * gamma[lane + 96] + beta[lane + 96];
    }
}

extern "C" void kernel_launch(void* const* d_in, const int* in_sizes, int n_in,
                              void* d_out, int out_size)
{
    const float* query = (const float*)d_in[0];
    const float* key   = (const float*)d_in[1];
    const float* value = (const float*)d_in[2];
    const int*   midx  = (const int*)d_in[3];
    const float* Wq = (const float*)d_in[4];  const float* bq = (const float*)d_in[5];
    const float* Wk = (const float*)d_in[6];  const float* bk = (const float*)d_in[7];
    const float* Wv = (const float*)d_in[8];  const float* bv = (const float*)d_in[9];
    const float* Wo = (const float*)d_in[10]; const float* bo = (const float*)d_in[11];
    const float* gamma = (const float*)d_in[12];
    const float* beta  = (const float*)d_in[13];

    int N = in_sizes[3];                    // element count of mask_idx = number of nodes
    int smem_bytes = SMEM_FLOATS * (int)sizeof(float);
    cudaFuncSetAttribute(mha_fused_kernel,
                         cudaFuncAttributeMaxDynamicSharedMemorySize, smem_bytes);
    int grid = (N + NB - 1) / NB;
    mha_fused_kernel<<<grid, THREADS, smem_bytes>>>(
        query, key, value, midx, Wq, bq, Wk, bk, Wv, bv, Wo, bo, gamma, beta,
        (float*)d_out, N);
}

// round 7
// speedup vs baseline: 1.3190x; 1.3190x over previous
#include <cuda_runtime.h>
#include <cstdint>
#include <math.h>

#define NB 8
#define THREADS 128
#define FEAT 128
#define SEQ 32
#define NHEAD 4
#define HDIM 32
#define LN_EPS 1e-5f
#define INV_SQRT_D 0.17677669529663687f

// dynamic smem layout (float offsets)
#define OFF_Q    0            // NB*128  query rows; reused as out rows
#define OFF_QP   1024         // NB*128  projected q; reused as wv
#define OFF_T    2048         // NB*4*128 t vectors
#define OFF_ATTN 6144         // NB*128  attn [j][s*4+h]
#define OFF_U    7168         // 4224: u[NB][4][128] (4096) ; also Wk head-chunk stage [128][33]
#define OFF_KB   11392        // 32*33 float4 = 4224 floats: pipelined key buffer
#define OFF_SB   15616        // NB*4 score bias
#define OFF_MI   15648        // NB mask values
#define SMEM_FLOATS 15664

__device__ __forceinline__ float warp_max(float v) {
#pragma unroll
    for (int o = 16; o; o >>= 1) v = fmaxf(v, __shfl_xor_sync(0xffffffffu, v, o));
    return v;
}
__device__ __forceinline__ float warp_sum(float v) {
#pragma unroll
    for (int o = 16; o; o >>= 1) v += __shfl_xor_sync(0xffffffffu, v, o);
    return v;
}

// async-stage Sa key rows (float4 granularity) into the key buffer
__device__ __forceinline__ void prefetch_keys(const float4* __restrict__ key4,
                                              uint32_t kb_smem_addr,
                                              int n, int Sa, int N, int tid) {
    for (int r = tid; r < Sa * 32; r += THREADS) {
        int s = r >> 5, k = r & 31;
        uint32_t dst = kb_smem_addr + (uint32_t)(s * 33 + k) * 16u;
        const float4* src = key4 + ((size_t)s * N + n) * 32 + k;
        asm volatile("cp.async.cg.shared.global [%0], [%1], 16;" :: "r"(dst), "l"(src));
    }
}

__global__ __launch_bounds__(THREADS)
void mha_fused_kernel(
    const float* __restrict__ query, const float* __restrict__ key,
    const float* __restrict__ value, const int* __restrict__ mask_idx,
    const float* __restrict__ Wq, const float* __restrict__ bq,
    const float* __restrict__ Wk, const float* __restrict__ bk,
    const float* __restrict__ Wv, const float* __restrict__ bv,
    const float* __restrict__ Wo, const float* __restrict__ bo,
    const float* __restrict__ gamma, const float* __restrict__ beta,
    float* __restrict__ out, int N)
{
    extern __shared__ float sm[];
    const int tid  = threadIdx.x;
    const int w    = tid >> 5;     // warp id == head id in score/softmax phase
    const int lane = tid & 31;
    const int n0   = blockIdx.x * NB;

    float* s_q    = sm + OFF_Q;
    float* s_qp   = sm + OFF_QP;
    float* s_t    = sm + OFF_T;
    float* s_attn = sm + OFF_ATTN;
    float* s_u    = sm + OFF_U;    // also Wk staging
    float* s_kb   = sm + OFF_KB;
    float* s_sb   = sm + OFF_SB;
    int*   s_mi   = (int*)(sm + OFF_MI);

    float4* s_kb4 = reinterpret_cast<float4*>(s_kb);
    const uint32_t kb_addr = (uint32_t)__cvta_generic_to_shared(s_kb);
    const float4* key4 = reinterpret_cast<const float4*>(key);

    // ---- stage query rows + mask values ----
#pragma unroll
    for (int j = 0; j < NB; j++) {
        int n = n0 + j;
        s_q[j * FEAT + tid] = (n < N) ? query[(size_t)n * FEAT + tid] : 0.f;
    }
    if (tid < NB) {
        int n = n0 + tid;
        s_mi[tid] = (n < N) ? mask_idx[n] : 0;
    }
    __syncthreads();

    // ---- kick off async prefetch of node 0's key rows (overlaps Phases A/B) ----
    {
        int m0 = s_mi[0];
        if (n0 < N && m0 > 0)              // m0==0 -> uniform attention, keys unused
            prefetch_keys(key4, kb_addr, n0, m0, N, tid);
        asm volatile("cp.async.commit_group;");
    }

    // ---- Phase A: qp = q @ Wq + bq  (thread = out feature, 8-node accumulators) ----
    {
        float acc[NB];
        float b = bq[tid];
#pragma unroll
        for (int j = 0; j < NB; j++) acc[j] = b;
#pragma unroll 4
        for (int f = 0; f < FEAT; f++) {
            float wgt = Wq[f * FEAT + tid];
#pragma unroll
            for (int j = 0; j < NB; j++) acc[j] = fmaf(s_q[j * FEAT + f], wgt, acc[j]);
        }
#pragma unroll
        for (int j = 0; j < NB; j++) s_qp[j * FEAT + tid] = acc[j];
    }
    __syncthreads();

    // ---- Phase B: t[j][h][f] = sum_d Wk[f, h*32+d] * qp[j, h*32+d] ----
    // Wk head chunk staged into the (not yet used) u region.
    for (int h = 0; h < NHEAD; h++) {
        for (int r = tid; r < FEAT * HDIM; r += THREADS) {
            int f = r >> 5, dd = r & 31;
            s_u[f * 33 + dd] = Wk[f * FEAT + h * HDIM + dd];
        }
        __syncthreads();
        float acc[NB];
#pragma unroll
        for (int j = 0; j < NB; j++) acc[j] = 0.f;
#pragma unroll
        for (int dd = 0; dd < HDIM; dd++) {
            float wgt = s_u[tid * 33 + dd];
#pragma unroll
            for (int j = 0; j < NB; j++)
                acc[j] = fmaf(s_qp[j * FEAT + h * HDIM + dd], wgt, acc[j]);
        }
#pragma unroll
        for (int j = 0; j < NB; j++) s_t[j * (NHEAD * FEAT) + h * FEAT + tid] = acc[j];
        __syncthreads();
    }

    // ---- score bias: sbias[j][h] = qp_h . bk_h ----
    if (tid < NB * NHEAD) {
        int j = tid >> 2, h = tid & 3;
        float s = 0.f;
        for (int dd = 0; dd < HDIM; dd++)
            s += s_qp[j * FEAT + h * HDIM + dd] * bk[h * HDIM + dd];
        s_sb[tid] = s;
    }
    // NOTE: the syncthreads at the top of the per-node loop makes s_sb visible.

    // ---- Per-node pipelined loop: scores + softmax + value aggregation ----
    for (int j = 0; j < NB; j++) {
        int n = n0 + j;
        bool valid = (n < N);
        int midx = valid ? s_mi[j] : 0;
        // midx==0: reference adds -1e9 which absorbs all scores in fp32 -> uniform softmax.
        bool uniform = (midx == 0);
        int Sa = uniform ? SEQ : midx;

        // wait for this node's keys; also fences s_sb (j==0) / u[j-1] writes
        asm volatile("cp.async.wait_group 0;" ::: "memory");
        __syncthreads();

        if (valid) {
            if (!uniform) {
                // scores: warp = head, lane = seq position; then warp softmax
                float sc = -1e30f;
                float p  = 0.f;
                if (lane < Sa) {
                    const float4* t4 = reinterpret_cast<const float4*>(s_t + j * (NHEAD * FEAT) + w * FEAT);
                    float ax = 0.f, ay = 0.f, az = 0.f, aw = 0.f;
#pragma unroll 8
                    for (int k = 0; k < FEAT / 4; k++) {
                        float4 kv = s_kb4[lane * 33 + k];
                        float4 tv = t4[k];
                        ax = fmaf(kv.x, tv.x, ax);
                        ay = fmaf(kv.y, tv.y, ay);
                        az = fmaf(kv.z, tv.z, az);
                        aw = fmaf(kv.w, tv.w, aw);
                    }
                    sc = (((ax + ay) + (az + aw)) + s_sb[j * 4 + w]) * INV_SQRT_D;
                }
                float m = warp_max(sc);
                if (lane < Sa) p = expf(sc - m);
                float denom = warp_sum(p);
                if (lane < Sa) s_attn[j * FEAT + lane * 4 + w] = p / denom;
            } else {
                s_attn[j * FEAT + lane * 4 + w] = 1.0f / SEQ;
            }
        }
        __syncthreads();   // attn visible to all; key-buffer reads complete

        // prefetch next node's keys (overlaps with value aggregation below)
        if (j + 1 < NB) {
            int n2 = n0 + j + 1;
            if (n2 < N) {
                int m2 = s_mi[j + 1];
                if (m2 > 0) prefetch_keys(key4, kb_addr, n2, m2, N, tid);
            }
        }
        asm volatile("cp.async.commit_group;");

        if (valid) {
            // u[j][h][f] = sum_{s<Sa} attn[s,h] * value[s,n,f]
            // value read DIRECTLY from global: thread=f is perfectly coalesced.
            const float* vb = value + (size_t)n * FEAT + tid;
            const float* ab = s_attn + j * FEAT;
            float a0 = 0.f, a1 = 0.f, a2 = 0.f, a3 = 0.f;
#pragma unroll 8
            for (int s = 0; s < Sa; s++) {
                float vv = __ldg(vb + (size_t)s * N * FEAT);
                float4 av = *reinterpret_cast<const float4*>(ab + s * 4);
                a0 = fmaf(av.x, vv, a0);
                a1 = fmaf(av.y, vv, a1);
                a2 = fmaf(av.z, vv, a2);
                a3 = fmaf(av.w, vv, a3);
            }
            s_u[j * (NHEAD * FEAT) + 0 * FEAT + tid] = a0;
            s_u[j * (NHEAD * FEAT) + 1 * FEAT + tid] = a1;
            s_u[j * (NHEAD * FEAT) + 2 * FEAT + tid] = a2;
            s_u[j * (NHEAD * FEAT) + 3 * FEAT + tid] = a3;
        }
    }
    __syncthreads();

    // ---- Phase E: wv[j][o] = bv[o] + sum_f u[j][o/32][f] * Wv[f,o]  (into s_qp) ----
    {
        float acc[NB];
        float b = bv[tid];
#pragma unroll
        for (int j = 0; j < NB; j++) acc[j] = b;
        const int h = tid >> 5;
#pragma unroll 4
        for (int f = 0; f < FEAT; f++) {
            float wgt = Wv[f * FEAT + tid];
#pragma unroll
            for (int j = 0; j < NB; j++)
                acc[j] = fmaf(s_u[j * (NHEAD * FEAT) + h * FEAT + f], wgt, acc[j]);
        }
#pragma unroll
        for (int j = 0; j < NB; j++) s_qp[j * FEAT + tid] = acc[j];   // s_wv
    }
    __syncthreads();

    // ---- Phase F: out[j][f'] = bo[f'] + sum_o wv[j][o] * Wo[o,f']  (into s_q) ----
    {
        float acc[NB];
        float b = bo[tid];
#pragma unroll
        for (int j = 0; j < NB; j++) acc[j] = b;
#pragma unroll 4
        for (int o = 0; o < FEAT; o++) {
            float wgt = Wo[o * FEAT + tid];
#pragma unroll
            for (int j = 0; j < NB; j++)
                acc[j] = fmaf(s_qp[j * FEAT + o], wgt, acc[j]);
        }
#pragma unroll
        for (int j = 0; j < NB; j++) s_q[j * FEAT + tid] = acc[j];    // s_out
    }
    __syncthreads();

    // ---- Phase G: LayerNorm + residual (warp handles nodes w, w+4) ----
    for (int j = w; j < NB; j += 4) {
        int n = n0 + j;
        if (n >= N) continue;
        float v0 = s_q[j * FEAT + lane];
        float v1 = s_q[j * FEAT + lane + 32];
        float v2 = s_q[j * FEAT + lane + 64];
        float v3 = s_q[j * FEAT + lane + 96];
        float mu = warp_sum(v0 + v1 + v2 + v3) * (1.f / FEAT);
        float d0 = v0 - mu, d1 = v1 - mu, d2 = v2 - mu, d3 = v3 - mu;
        float var = warp_sum(d0 * d0 + d1 * d1 + d2 * d2 + d3 * d3) * (1.f / FEAT);
        float rstd = rsqrtf(var + LN_EPS);
        size_t base = (size_t)n * FEAT;
        out[base + lane]      = query[base + lane]      + d0 * rstd * gamma[lane]      + beta[lane];
        out[base + lane + 32] = query[base + lane + 32] + d1 * rstd * gamma[lane + 32] + beta[lane + 32];
        out[base + lane + 64] = query[base + lane + 64] + d2 * rstd * gamma[lane + 64] + beta[lane + 64];
        out[base + lane + 96] = query[base + lane + 96] + d3 * rstd * gamma[lane + 96] + beta[lane + 96];
    }
}

extern "C" void kernel_launch(void* const* d_in, const int* in_sizes, int n_in,
                              void* d_out, int out_size)
{
    const float* query = (const float*)d_in[0];
    const float* key   = (const float*)d_in[1];
    const float* value = (const float*)d_in[2];
    const int*   midx  = (const int*)d_in[3];
    const float* Wq = (const float*)d_in[4];  const float* bq = (const float*)d_in[5];
    const float* Wk = (const float*)d_in[6];  const float* bk = (const float*)d_in[7];
    const float* Wv = (const float*)d_in[8];  const float* bv = (const float*)d_in[9];
    const float* Wo = (const float*)d_in[10]; const float* bo = (const float*)d_in[11];
    const float* gamma = (const float*)d_in[12];
    const float* beta  = (const float*)d_in[13];

    int N = in_sizes[3];                    // element count of mask_idx = number of nodes
    int smem_bytes = SMEM_FLOATS * (int)sizeof(float);
    cudaFuncSetAttribute(mha_fused_kernel,
                         cudaFuncAttributeMaxDynamicSharedMemorySize, smem_bytes);
    int grid = (N + NB - 1) / NB;
    mha_fused_kernel<<<grid, THREADS, smem_bytes>>>(
        query, key, value, midx, Wq, bq, Wk, bk, Wv, bv, Wo, bo, gamma, beta,
        (float*)d_out, N);
}

// round 9
// speedup vs baseline: 1.6675x; 1.2643x over previous
#include <cuda_runtime.h>
#include <cstdint>
#include <math.h>

#define NB 8
#define THREADS 128
#define FEAT 128
#define SEQ 32
#define NHEAD 4
#define HDIM 32
#define LN_EPS 1e-5f
#define INV_SQRT_D 0.17677669529663687f

// dynamic smem layout (float offsets)
#define OFF_Q    0            // NB*128 query rows; reused as out rows (Phase F+)
#define OFF_QP   1024         // NB*128 qp; reused as attn [j][s*4+h] in loop; reused as wv (Phase E)
#define OFF_T    2048         // NB*4*128 t vectors
#define OFF_U    6144         // NB*4*128 aggregated values
#define OFF_KB   10240        // 31 rows * 132 = 4092 floats: pipelined key buffer
#define OFF_VB   14336        // 32 rows * 132 = 4224 floats: pipelined value buffer; also Wk stage [128][33]
#define OFF_SB   18560        // NB*4 score bias
#define OFF_MI   18592        // NB mask values
#define SMEM_FLOATS 18624     // 74496 bytes -> 3 CTAs/SM

__device__ __forceinline__ float warp_max(float v) {
#pragma unroll
    for (int o = 16; o; o >>= 1) v = fmaxf(v, __shfl_xor_sync(0xffffffffu, v, o));
    return v;
}
__device__ __forceinline__ float warp_sum(float v) {
#pragma unroll
    for (int o = 16; o; o >>= 1) v += __shfl_xor_sync(0xffffffffu, v, o);
    return v;
}

// async-stage `rows` rows of a [SEQ, N, FEAT] tensor for node n into smem (stride 33 float4)
__device__ __forceinline__ void prefetch_rows(const float4* __restrict__ src4,
                                              uint32_t dst_smem_addr,
                                              int n, int rows, int N, int tid) {
    for (int r = tid; r < rows * 32; r += THREADS) {
        int s = r >> 5, k = r & 31;
        uint32_t dst = dst_smem_addr + (uint32_t)(s * 33 + k) * 16u;
        const float4* src = src4 + ((size_t)s * N + n) * 32 + k;
        asm volatile("cp.async.cg.shared.global [%0], [%1], 16;" :: "r"(dst), "l"(src));
    }
}

__global__ __launch_bounds__(THREADS)
void mha_fused_kernel(
    const float* __restrict__ query, const float* __restrict__ key,
    const float* __restrict__ value, const int* __restrict__ mask_idx,
    const float* __restrict__ Wq, const float* __restrict__ bq,
    const float* __restrict__ Wk, const float* __restrict__ bk,
    const float* __restrict__ Wv, const float* __restrict__ bv,
    const float* __restrict__ Wo, const float* __restrict__ bo,
    const float* __restrict__ gamma, const float* __restrict__ beta,
    float* __restrict__ out, int N)
{
    extern __shared__ float sm[];
    const int tid  = threadIdx.x;
    const int w    = tid >> 5;     // warp id == head id in score/softmax phase
    const int lane = tid & 31;
    const int n0   = blockIdx.x * NB;

    float* s_q    = sm + OFF_Q;
    float* s_qp   = sm + OFF_QP;   // -> attn -> wv
    float* s_t    = sm + OFF_T;
    float* s_u    = sm + OFF_U;
    float* s_kb   = sm + OFF_KB;
    float* s_vb   = sm + OFF_VB;   // also Wk staging before the loop
    float* s_sb   = sm + OFF_SB;
    int*   s_mi   = (int*)(sm + OFF_MI);

    float* s_attn = s_qp;          // overlay (qp dead after sbias)
    float4* s_kb4 = reinterpret_cast<float4*>(s_kb);
    const uint32_t kb_addr = (uint32_t)__cvta_generic_to_shared(s_kb);
    const uint32_t vb_addr = (uint32_t)__cvta_generic_to_shared(s_vb);
    const float4* key4 = reinterpret_cast<const float4*>(key);
    const float4* val4 = reinterpret_cast<const float4*>(value);

    // ---- stage query rows + mask values ----
#pragma unroll
    for (int j = 0; j < NB; j++) {
        int n = n0 + j;
        s_q[j * FEAT + tid] = (n < N) ? query[(size_t)n * FEAT + tid] : 0.f;
    }
    if (tid < NB) {
        int n = n0 + tid;
        s_mi[tid] = (n < N) ? mask_idx[n] : 0;
    }
    __syncthreads();

    // ---- kick off async prefetch of node 0's key rows (overlaps Phases A/B) ----
    {
        int m0 = s_mi[0];
        if (n0 < N && m0 > 0)              // m0==0 -> uniform attention, keys unused
            prefetch_rows(key4, kb_addr, n0, m0, N, tid);
        asm volatile("cp.async.commit_group;");
    }

    // ---- Phase A: qp = q @ Wq + bq  (thread = out feature, 8-node accumulators) ----
    {
        float acc[NB];
        float b = bq[tid];
#pragma unroll
        for (int j = 0; j < NB; j++) acc[j] = b;
#pragma unroll 4
        for (int f = 0; f < FEAT; f++) {
            float wgt = Wq[f * FEAT + tid];
#pragma unroll
            for (int j = 0; j < NB; j++) acc[j] = fmaf(s_q[j * FEAT + f], wgt, acc[j]);
        }
#pragma unroll
        for (int j = 0; j < NB; j++) s_qp[j * FEAT + tid] = acc[j];
    }
    __syncthreads();

    // ---- Phase B: t[j][h][f] = sum_d Wk[f, h*32+d] * qp[j, h*32+d] ----
    // Wk head chunk staged into the V buffer (free until the loop starts).
    for (int h = 0; h < NHEAD; h++) {
        for (int r = tid; r < FEAT * HDIM; r += THREADS) {
            int f = r >> 5, dd = r & 31;
            s_vb[f * 33 + dd] = Wk[f * FEAT + h * HDIM + dd];
        }
        __syncthreads();
        float acc[NB];
#pragma unroll
        for (int j = 0; j < NB; j++) acc[j] = 0.f;
#pragma unroll
        for (int dd = 0; dd < HDIM; dd++) {
            float wgt = s_vb[tid * 33 + dd];
#pragma unroll
            for (int j = 0; j < NB; j++)
                acc[j] = fmaf(s_qp[j * FEAT + h * HDIM + dd], wgt, acc[j]);
        }
#pragma unroll
        for (int j = 0; j < NB; j++) s_t[j * (NHEAD * FEAT) + h * FEAT + tid] = acc[j];
        __syncthreads();
    }

    // ---- score bias: sbias[j][h] = qp_h . bk_h ----
    if (tid < NB * NHEAD) {
        int j = tid >> 2, h = tid & 3;
        float s = 0.f;
        for (int dd = 0; dd < HDIM; dd++)
            s += s_qp[j * FEAT + h * HDIM + dd] * bk[h * HDIM + dd];
        s_sb[tid] = s;
    }
    // visibility of s_sb (and the end of Wk staging use) is established by the
    // first barrier inside the loop below.

    // ---- Per-node pipelined loop ----
    // iter j: wait K[j] | bar | issue V[j] | scores[j] | wait V[j] | bar | issue K[j+1] | agg[j]
    for (int j = 0; j < NB; j++) {
        int n = n0 + j;
        bool valid = (n < N);
        int midx = valid ? s_mi[j] : 0;
        // midx==0: reference adds -1e9 which absorbs all scores in fp32 -> uniform softmax.
        bool uniform = (midx == 0);
        int Sa = uniform ? SEQ : midx;     // rows for V aggregation

        // ---- wait K[j]; fence prior-iteration smem writes ----
        asm volatile("cp.async.wait_group 0;" ::: "memory");
        __syncthreads();                   // K visible; V buffer free; attn[j-1] consumed

        // ---- issue V[j] into V buffer (latency covered by scores below) ----
        if (valid)
            prefetch_rows(val4, vb_addr, n, Sa, N, tid);
        asm volatile("cp.async.commit_group;");

        // ---- scores + softmax (or uniform) ----
        if (valid) {
            if (!uniform) {
                float sc = -1e30f;
                float p  = 0.f;
                if (lane < midx) {
                    const float4* t4 = reinterpret_cast<const float4*>(s_t + j * (NHEAD * FEAT) + w * FEAT);
                    float ax = 0.f, ay = 0.f, az = 0.f, aw = 0.f;
#pragma unroll 8
                    for (int k = 0; k < FEAT / 4; k++) {
                        float4 kv = s_kb4[lane * 33 + k];
                        float4 tv = t4[k];
                        ax = fmaf(kv.x, tv.x, ax);
                        ay = fmaf(kv.y, tv.y, ay);
                        az = fmaf(kv.z, tv.z, az);
                        aw = fmaf(kv.w, tv.w, aw);
                    }
                    sc = (((ax + ay) + (az + aw)) + s_sb[j * 4 + w]) * INV_SQRT_D;
                }
                float m = warp_max(sc);
                if (lane < midx) p = expf(sc - m);
                float denom = warp_sum(p);
                if (lane < midx) s_attn[j * FEAT + lane * 4 + w] = p / denom;
            } else {
                s_attn[j * FEAT + lane * 4 + w] = 1.0f / SEQ;
            }
        }

        // ---- wait V[j]; make attn + V visible; K buffer reads complete ----
        asm volatile("cp.async.wait_group 0;" ::: "memory");
        __syncthreads();

        // ---- issue K[j+1] (latency covered by aggregation below) ----
        if (j + 1 < NB) {
            int n2 = n0 + j + 1;
            if (n2 < N) {
                int m2 = s_mi[j + 1];
                if (m2 > 0) prefetch_rows(key4, kb_addr, n2, m2, N, tid);
            }
        }
        asm volatile("cp.async.commit_group;");

        // ---- u[j][h][f] = sum_{s<Sa} attn[s,h] * V_smem[s,f]  (thread = f) ----
        if (valid) {
            const float* ab = s_attn + j * FEAT;
            float a0 = 0.f, a1 = 0.f, a2 = 0.f, a3 = 0.f;
#pragma unroll 8
            for (int s = 0; s < Sa; s++) {
                float vv = s_vb[s * 132 + tid];
                float4 av = *reinterpret_cast<const float4*>(ab + s * 4);
                a0 = fmaf(av.x, vv, a0);
                a1 = fmaf(av.y, vv, a1);
                a2 = fmaf(av.z, vv, a2);
                a3 = fmaf(av.w, vv, a3);
            }
            s_u[j * (NHEAD * FEAT) + 0 * FEAT + tid] = a0;
            s_u[j * (NHEAD * FEAT) + 1 * FEAT + tid] = a1;
            s_u[j * (NHEAD * FEAT) + 2 * FEAT + tid] = a2;
            s_u[j * (NHEAD * FEAT) + 3 * FEAT + tid] = a3;
        }
    }
    __syncthreads();

    // ---- Phase E: wv[j][o] = bv[o] + sum_f u[j][o/32][f] * Wv[f,o]  (into s_qp overlay) ----
    {
        float acc[NB];
        float b = bv[tid];
#pragma unroll
        for (int j = 0; j < NB; j++) acc[j] = b;
        const int h = tid >> 5;
#pragma unroll 4
        for (int f = 0; f < FEAT; f++) {
            float wgt = Wv[f * FEAT + tid];
#pragma unroll
            for (int j = 0; j < NB; j++)
                acc[j] = fmaf(s_u[j * (NHEAD * FEAT) + h * FEAT + f], wgt, acc[j]);
        }
#pragma unroll
        for (int j = 0; j < NB; j++) s_qp[j * FEAT + tid] = acc[j];   // wv
    }
    __syncthreads();

    // ---- Phase F: out[j][f'] = bo[f'] + sum_o wv[j][o] * Wo[o,f']  (into s_q overlay) ----
    {
        float acc[NB];
        float b = bo[tid];
#pragma unroll
        for (int j = 0; j < NB; j++) acc[j] = b;
#pragma unroll 4
        for (int o = 0; o < FEAT; o++) {
            float wgt = Wo[o * FEAT + tid];
#pragma unroll
            for (int j = 0; j < NB; j++)
                acc[j] = fmaf(s_qp[j * FEAT + o], wgt, acc[j]);
        }
#pragma unroll
        for (int j = 0; j < NB; j++) s_q[j * FEAT + tid] = acc[j];    // out (pre-LN)
    }
    __syncthreads();

    // ---- Phase G: LayerNorm + residual (warp handles nodes w, w+4) ----
    for (int j = w; j < NB; j += 4) {
        int n = n0 + j;
        if (n >= N) continue;
        float v0 = s_q[j * FEAT + lane];
        float v1 = s_q[j * FEAT + lane + 32];
        float v2 = s_q[j * FEAT + lane + 64];
        float v3 = s_q[j * FEAT + lane + 96];
        float mu = warp_sum(v0 + v1 + v2 + v3) * (1.f / FEAT);
        float d0 = v0 - mu, d1 = v1 - mu, d2 = v2 - mu, d3 = v3 - mu;
        float var = warp_sum(d0 * d0 + d1 * d1 + d2 * d2 + d3 * d3) * (1.f / FEAT);
        float rstd = rsqrtf(var + LN_EPS);
        size_t base = (size_t)n * FEAT;
        out[base + lane]      = query[base + lane]      + d0 * rstd * gamma[lane]      + beta[lane];
        out[base + lane + 32] = query[base + lane + 32] + d1 * rstd * gamma[lane + 32] + beta[lane + 32];
        out[base + lane + 64] = query[base + lane + 64] + d2 * rstd * gamma[lane + 64] + beta[lane + 64];
        out[base + lane + 96] = query[base + lane + 96] + d3 * rstd * gamma[lane + 96] + beta[lane + 96];
    }
}

extern "C" void kernel_launch(void* const* d_in, const int* in_sizes, int n_in,
                              void* d_out, int out_size)
{
    const float* query = (const float*)d_in[0];
    const float* key   = (const float*)d_in[1];
    const float* value = (const float*)d_in[2];
    const int*   midx  = (const int*)d_in[3];
    const float* Wq = (const float*)d_in[4];  const float* bq = (const float*)d_in[5];
    const float* Wk = (const float*)d_in[6];  const float* bk = (const float*)d_in[7];
    const float* Wv = (const float*)d_in[8];  const float* bv = (const float*)d_in[9];
    const float* Wo = (const float*)d_in[10]; const float* bo = (const float*)d_in[11];
    const float* gamma = (const float*)d_in[12];
    const float* beta  = (const float*)d_in[13];

    int N = in_sizes[3];                    // element count of mask_idx = number of nodes
    int smem_bytes = SMEM_FLOATS * (int)sizeof(float);
    cudaFuncSetAttribute(mha_fused_kernel,
                         cudaFuncAttributeMaxDynamicSharedMemorySize, smem_bytes);
    int grid = (N + NB - 1) / NB;
    mha_fused_kernel<<<grid, THREADS, smem_bytes>>>(
        query, key, value, midx, Wq, bq, Wk, bk, Wv, bv, Wo, bo, gamma, beta,
        (float*)d_out, N);
}